// round 9
// baseline (speedup 1.0000x reference)
#include <cuda_runtime.h>
#include <cuda_bf16.h>

// MedianFilter1D: x[16, 64, 16384] fp32, window k=9, zero padding.
// 1024 rows x 16384 = 2,097,152 chunks of 8 outputs.
//
// Round 9 — occupancy-preserving pipeline + write-through stores.
//  * ITERS=2, GRID=4096: both LDG.256 issued before any compute (MLP=2),
//    fewer regs than R8's 4-deep version -> higher occupancy -> more
//    in-flight loads chip-wide.
//  * st.global.wt: R8 left ~67 MB dirty in L2 at kernel end; that drain
//    serialized against the next replay (kernel 19.7us vs harness 23.0us).
//    Write-through pays the write bandwidth inside the kernel, overlapped
//    with reads.
//
// Compute (80 ops / 8 outputs): sort 7 adjacent pairs; sorted-4 runs via
// 3-CE merge of two sorted pairs; ranks 3,4 of each window-pair's shared 8
// via pruned odd-even merge(4,4); median9 = clamp(inserted, s3, s4).

#define CE(a, b) { float _lo = fminf(a, b); float _hi = fmaxf(a, b); (a) = _lo; (b) = _hi; }

__device__ __forceinline__ void ld_in8(const float* p, float* v)
{
    asm volatile(
        "ld.global.nc.L2::evict_last.v8.f32 {%0,%1,%2,%3,%4,%5,%6,%7}, [%8];"
        : "=f"(v[0]), "=f"(v[1]), "=f"(v[2]), "=f"(v[3]),
          "=f"(v[4]), "=f"(v[5]), "=f"(v[6]), "=f"(v[7])
        : "l"(p));
}

__device__ __forceinline__ void st_out_wt(float* p, const float* o)
{
    asm volatile("st.global.wt.v4.f32 [%0], {%1,%2,%3,%4};"
                 :: "l"(p), "f"(o[0]), "f"(o[1]), "f"(o[2]), "f"(o[3]) : "memory");
    asm volatile("st.global.wt.v4.f32 [%0], {%1,%2,%3,%4};"
                 :: "l"(p + 4), "f"(o[4]), "f"(o[5]), "f"(o[6]), "f"(o[7]) : "memory");
}

static constexpr int L       = 16384;
static constexpr int ROWS    = 16 * 64;
static constexpr int TPB     = 256;
static constexpr int NCHUNK  = ROWS * (L / 8);        // 2,097,152
static constexpr int GRID    = 4096;
static constexpr int STRIDE  = GRID * TPB;            // 1,048,576 threads
static constexpr int ITERS   = NCHUNK / STRIDE;       // 2

__device__ __forceinline__ void process_chunk(
    const float* __restrict__ x, float* __restrict__ y,
    const float* own, int c, int lane)
{
    const unsigned FULL = 0xFFFFFFFFu;
    float v[16];
    #pragma unroll
    for (int i = 0; i < 8; i++) v[4 + i] = own[i];

    // Halos from neighbor lanes (consecutive c across lanes).
    float4 lh, rh;
    lh.x = __shfl_up_sync(FULL, v[8],  1);
    lh.y = __shfl_up_sync(FULL, v[9],  1);
    lh.z = __shfl_up_sync(FULL, v[10], 1);
    lh.w = __shfl_up_sync(FULL, v[11], 1);
    rh.x = __shfl_down_sync(FULL, v[4], 1);
    rh.y = __shfl_down_sync(FULL, v[5], 1);
    rh.z = __shfl_down_sync(FULL, v[6], 1);
    rh.w = __shfl_down_sync(FULL, v[7], 1);

    int cm = c & 2047;   // chunk position within its row
    if (lane == 0) {
        if (cm != 0) lh = __ldg(reinterpret_cast<const float4*>(x + 8 * (size_t)c - 4));
        else         lh = make_float4(0.f, 0.f, 0.f, 0.f);
    }
    if (lane == 31) {
        if (cm != 2047) rh = __ldg(reinterpret_cast<const float4*>(x + 8 * (size_t)c + 8));
        else            rh = make_float4(0.f, 0.f, 0.f, 0.f);
    }
    v[0]  = lh.x; v[1]  = lh.y; v[2]  = lh.z; v[3]  = lh.w;
    v[12] = rh.x; v[13] = rh.y; v[14] = rh.z; v[15] = rh.w;

    // Sorted pairs P_j = sorted(v[2j+1], v[2j+2]), j = 0..6.
    float pl[7], ph[7];
    #pragma unroll
    for (int j = 0; j < 7; j++) {
        pl[j] = fminf(v[2*j + 1], v[2*j + 2]);
        ph[j] = fmaxf(v[2*j + 1], v[2*j + 2]);
    }

    // Runs R[i] = sorted-4 of v[2i+1 .. 2i+5) = merge(P_i, P_{i+1}), 3 CE.
    float R[6][4];
    #pragma unroll
    for (int i = 0; i < 6; i++) {
        float x0 = pl[i], x1 = ph[i], x2 = pl[i + 1], x3 = ph[i + 1];
        CE(x0, x2) CE(x1, x3) CE(x1, x2)
        R[i][0] = x0; R[i][1] = x1; R[i][2] = x2; R[i][3] = x3;
    }

    float o[8];
    #pragma unroll
    for (int j = 0; j < 4; j++) {
        int b = 2 * j;
        const float* A = R[j];       // sorted v[b+1 .. b+5)
        const float* B = R[j + 2];   // sorted v[b+5 .. b+9)
        float e2 = fmaxf(fmaxf(A[0], B[0]), fminf(A[2], B[2]));
        float o1 = fminf(fmaxf(A[1], B[1]), fminf(A[3], B[3]));
        float s3 = fminf(o1, e2);
        float s4 = fmaxf(o1, e2);
        o[b]     = fminf(fmaxf(v[b],     s3), s4);
        o[b + 1] = fminf(fmaxf(v[b + 9], s3), s4);
    }

    st_out_wt(y + 8 * (size_t)c, o);
}

__global__ __launch_bounds__(TPB)
void median9_kernel(const float* __restrict__ x, float* __restrict__ y)
{
    int t    = blockIdx.x * TPB + threadIdx.x;
    int lane = threadIdx.x & 31;

    static_assert(ITERS == 2, "hand-unrolled for 2 iterations");

    float A[8], B[8];
    ld_in8(x + 8 * (size_t)t, A);                   // load #0
    ld_in8(x + 8 * (size_t)(t + STRIDE), B);        // load #1 (both in flight)
    process_chunk(x, y, A, t, lane);                // compute #0
    process_chunk(x, y, B, t + STRIDE, lane);       // compute #1
}

extern "C" void kernel_launch(void* const* d_in, const int* in_sizes, int n_in,
                              void* d_out, int out_size)
{
    const float* x = (const float*)d_in[0];
    float* y = (float*)d_out;
    median9_kernel<<<GRID, TPB>>>(x, y);
}

// round 10
// speedup vs baseline: 1.0986x; 1.0986x over previous
#include <cuda_runtime.h>
#include <cuda_bf16.h>

// MedianFilter1D: x[16, 64, 16384] fp32, window k=9, zero padding.
// 1024 rows x 16384 = 2,097,152 chunks of 8 outputs.
//
// Round 10 — R8 (best measured: 4-deep grid-strided pipeline, kernel 19.7us)
// + forced occupancy. R9 taught: st.global.wt hurts (defeats L2 write
// combining); __launch_bounds__(TPB) alone doesn't cap regs (ptxas picked
// 47-48 every time -> occ pinned at ~50%). Fix: __launch_bounds__(256, 6)
// caps regs at 42 -> 48 warps/SM (75% occ) -> more LDG.256 in flight.
//
// Compute: sort 7 adjacent pairs; sorted-4 runs via 3-CE merge of sorted
// pairs; ranks 3,4 of each window-pair's shared 8 via pruned odd-even
// merge(4,4); median9 = clamp(inserted, s3, s4).

#define CE(a, b) { float _lo = fminf(a, b); float _hi = fmaxf(a, b); (a) = _lo; (b) = _hi; }

__device__ __forceinline__ void ld_in8(const float* p, float* v)
{
    asm volatile(
        "ld.global.nc.L2::evict_last.v8.f32 {%0,%1,%2,%3,%4,%5,%6,%7}, [%8];"
        : "=f"(v[0]), "=f"(v[1]), "=f"(v[2]), "=f"(v[3]),
          "=f"(v[4]), "=f"(v[5]), "=f"(v[6]), "=f"(v[7])
        : "l"(p));
}

__device__ __forceinline__ void st_out8(float* p, const float* o)
{
    asm volatile(
        "st.global.L2::evict_first.v8.f32 [%0], {%1,%2,%3,%4,%5,%6,%7,%8};"
        :: "l"(p),
           "f"(o[0]), "f"(o[1]), "f"(o[2]), "f"(o[3]),
           "f"(o[4]), "f"(o[5]), "f"(o[6]), "f"(o[7])
        : "memory");
}

static constexpr int L       = 16384;
static constexpr int ROWS    = 16 * 64;
static constexpr int TPB     = 256;
static constexpr int NCHUNK  = ROWS * (L / 8);        // 2,097,152
static constexpr int GRID    = 2048;
static constexpr int STRIDE  = GRID * TPB;            // 524,288 threads
static constexpr int ITERS   = NCHUNK / STRIDE;       // 4

__device__ __forceinline__ void process_chunk(
    const float* __restrict__ x, float* __restrict__ y,
    const float* own, int c, int lane)
{
    const unsigned FULL = 0xFFFFFFFFu;
    float v[16];
    #pragma unroll
    for (int i = 0; i < 8; i++) v[4 + i] = own[i];

    // Halos from neighbor lanes (consecutive c across lanes).
    float4 lh, rh;
    lh.x = __shfl_up_sync(FULL, v[8],  1);
    lh.y = __shfl_up_sync(FULL, v[9],  1);
    lh.z = __shfl_up_sync(FULL, v[10], 1);
    lh.w = __shfl_up_sync(FULL, v[11], 1);
    rh.x = __shfl_down_sync(FULL, v[4], 1);
    rh.y = __shfl_down_sync(FULL, v[5], 1);
    rh.z = __shfl_down_sync(FULL, v[6], 1);
    rh.w = __shfl_down_sync(FULL, v[7], 1);

    int cm = c & 2047;   // chunk position within its row
    if (lane == 0) {
        if (cm != 0) lh = __ldg(reinterpret_cast<const float4*>(x + 8 * (size_t)c - 4));
        else         lh = make_float4(0.f, 0.f, 0.f, 0.f);
    }
    if (lane == 31) {
        if (cm != 2047) rh = __ldg(reinterpret_cast<const float4*>(x + 8 * (size_t)c + 8));
        else            rh = make_float4(0.f, 0.f, 0.f, 0.f);
    }
    v[0]  = lh.x; v[1]  = lh.y; v[2]  = lh.z; v[3]  = lh.w;
    v[12] = rh.x; v[13] = rh.y; v[14] = rh.z; v[15] = rh.w;

    // Sorted pairs P_j = sorted(v[2j+1], v[2j+2]), j = 0..6.
    float pl[7], ph[7];
    #pragma unroll
    for (int j = 0; j < 7; j++) {
        pl[j] = fminf(v[2*j + 1], v[2*j + 2]);
        ph[j] = fmaxf(v[2*j + 1], v[2*j + 2]);
    }

    // Runs R[i] = sorted-4 of v[2i+1 .. 2i+5) = merge(P_i, P_{i+1}), 3 CE.
    float R[6][4];
    #pragma unroll
    for (int i = 0; i < 6; i++) {
        float x0 = pl[i], x1 = ph[i], x2 = pl[i + 1], x3 = ph[i + 1];
        CE(x0, x2) CE(x1, x3) CE(x1, x2)
        R[i][0] = x0; R[i][1] = x1; R[i][2] = x2; R[i][3] = x3;
    }

    float o[8];
    #pragma unroll
    for (int j = 0; j < 4; j++) {
        int b = 2 * j;
        const float* A = R[j];       // sorted v[b+1 .. b+5)
        const float* B = R[j + 2];   // sorted v[b+5 .. b+9)
        float e2 = fmaxf(fmaxf(A[0], B[0]), fminf(A[2], B[2]));
        float o1 = fminf(fmaxf(A[1], B[1]), fminf(A[3], B[3]));
        float s3 = fminf(o1, e2);
        float s4 = fmaxf(o1, e2);
        o[b]     = fminf(fmaxf(v[b],     s3), s4);
        o[b + 1] = fminf(fmaxf(v[b + 9], s3), s4);
    }

    st_out8(y + 8 * (size_t)c, o);
}

__global__ __launch_bounds__(TPB, 6)
void median9_kernel(const float* __restrict__ x, float* __restrict__ y)
{
    int t    = blockIdx.x * TPB + threadIdx.x;
    int lane = threadIdx.x & 31;

    float A[8], B[8];
    int c = t;
    ld_in8(x + 8 * (size_t)c, A);                 // prologue load

    static_assert(ITERS == 4, "pipeline is hand-unrolled for 4 iterations");

    ld_in8(x + 8 * (size_t)(c + STRIDE), B);      // load #1 in flight
    process_chunk(x, y, A, c, lane);              // compute #0
    c += STRIDE;

    ld_in8(x + 8 * (size_t)(c + STRIDE), A);      // load #2 in flight
    process_chunk(x, y, B, c, lane);              // compute #1
    c += STRIDE;

    ld_in8(x + 8 * (size_t)(c + STRIDE), B);      // load #3 in flight
    process_chunk(x, y, A, c, lane);              // compute #2
    c += STRIDE;

    process_chunk(x, y, B, c, lane);              // compute #3
}

extern "C" void kernel_launch(void* const* d_in, const int* in_sizes, int n_in,
                              void* d_out, int out_size)
{
    const float* x = (const float*)d_in[0];
    float* y = (float*)d_out;
    median9_kernel<<<GRID, TPB>>>(x, y);
}